// round 17
// baseline (speedup 1.0000x reference)
#include <cuda_runtime.h>
#include <cuda_bf16.h>
#include <cuda_fp16.h>
#include <math.h>

// Problem constants
#define BATCH   2
#define SEQLEN  2048
#define DMODEL  2048
#define NHEADS  16
#define DHEAD   128
#define MTOT    (BATCH * SEQLEN)      // 4096

typedef unsigned int u32;
typedef unsigned short u16;

// ---- fp16 split helper: v = hi + lo, residual ~2^-22
__device__ __forceinline__ void split1h(float v, __half& h, __half& l) {
    h = __float2half(v);
    l = __float2half(v - __half2float(h));
}
__device__ __forceinline__ u32 pack2h(float lo, float hi) {
    u32 r; asm("cvt.rn.f16x2.f32 %0, %1, %2;" : "=r"(r) : "f"(hi), "f"(lo)); return r;
}
__device__ __forceinline__ float ex2f(float x) {
    float y; asm("ex2.approx.f32 %0, %1;" : "=f"(y) : "f"(x)); return y;
}
// ---- cp.async helpers (16B; smem dst MUST be 16B-aligned: row pitch % 16B == 0)
__device__ __forceinline__ void cpa16(u32 dst_smem, const void* src) {
    asm volatile("cp.async.cg.shared.global [%0], [%1], 16;" :: "r"(dst_smem), "l"(src));
}
#define CP_COMMIT() asm volatile("cp.async.commit_group;")
#define CP_WAIT0()  asm volatile("cp.async.wait_group 0;")

// ---- scratch (device globals; device-side refs only)
__device__ __half gx16[(size_t)MTOT * DMODEL];          // x as fp16
__device__ __half gq16[(size_t)MTOT * DMODEL];          // q single fp16 [b,h,s,d]
__device__ __half gk16[(size_t)MTOT * DMODEL];          // k single fp16 [b,h,s,d]
__device__ __half gv16[(size_t)MTOT * DMODEL];          // v single fp16 [b,h,s,d]
__device__ __half gz16[(size_t)MTOT * DMODEL];          // z as fp16 [b*s][h*d]
// QKV weights transposed per head, fp16 split: [which][h][n(128)][k(2048)]
__device__ __half gw16_hi[(size_t)3 * NHEADS * DHEAD * DMODEL];
__device__ __half gw16_lo[(size_t)3 * NHEADS * DHEAD * DMODEL];
// W_O transposed, single fp16: [n(2048)][k(2048)]
__device__ __half gwo16[(size_t)DMODEL * DMODEL];

// ---------------------------------------------------------------------------
// Prep kernels
// ---------------------------------------------------------------------------
__global__ void __launch_bounds__(256) split_x_kernel(const float* __restrict__ x)
{
    size_t i = (size_t)blockIdx.x * blockDim.x + threadIdx.x;
    float2 v = ((const float2*)x)[i];
    __half2 hp; hp.x = __float2half(v.x); hp.y = __float2half(v.y);
    ((__half2*)gx16)[i] = hp;
}

__global__ void split_w_kernel(const float* __restrict__ Wq,
                               const float* __restrict__ Wk,
                               const float* __restrict__ Wv)
{
    const int which = blockIdx.z / NHEADS;
    const int h     = blockIdx.z % NHEADS;
    const float* W = ((which == 0) ? Wq : (which == 1) ? Wk : Wv)
                     + (size_t)h * DMODEL * DHEAD;
    const int k0 = blockIdx.x * 32;
    const int n0 = blockIdx.y * 32;

    __shared__ float tile[32][33];
    const int tx = threadIdx.x, ty = threadIdx.y;
#pragma unroll
    for (int r = 0; r < 4; r++)
        tile[ty + 8 * r][tx] = W[(size_t)(k0 + ty + 8 * r) * DHEAD + n0 + tx];
    __syncthreads();
    const size_t base = ((size_t)(which * NHEADS + h) * DHEAD);
#pragma unroll
    for (int r = 0; r < 4; r++) {
        float v = tile[tx][ty + 8 * r];
        __half hh, ll; split1h(v, hh, ll);
        size_t idx = (base + n0 + ty + 8 * r) * DMODEL + k0 + tx;
        gw16_hi[idx] = hh; gw16_lo[idx] = ll;
    }
}

__global__ void split_wo_kernel(const float* __restrict__ Wo)
{
    const int k0 = blockIdx.x * 32;
    const int n0 = blockIdx.y * 32;
    __shared__ float tile[32][33];
    const int tx = threadIdx.x, ty = threadIdx.y;
#pragma unroll
    for (int r = 0; r < 4; r++)
        tile[ty + 8 * r][tx] = Wo[(size_t)(k0 + ty + 8 * r) * DMODEL + n0 + tx];
    __syncthreads();
#pragma unroll
    for (int r = 0; r < 4; r++) {
        float v = tile[tx][ty + 8 * r];
        size_t idx = (size_t)(n0 + ty + 8 * r) * DMODEL + k0 + tx;
        gwo16[idx] = __float2half(v);
    }
}

// ---------------------------------------------------------------------------
// fp16 GEMM cores. Block 256 thr (8 warps, 4x2), tile 128x128, K step 32,
// cp.async 2-stage, one sync/iter, 2 CTAs/SM.
// ---------------------------------------------------------------------------
#define KC   32
#define SSTR 40
#define GARR  (128 * SSTR)

#define MMA_F16(c, a, b) \
    asm volatile("mma.sync.aligned.m16n8k16.row.col.f32.f16.f16.f32 " \
        "{%0,%1,%2,%3}, {%4,%5,%6,%7}, {%8,%9}, {%0,%1,%2,%3};" \
        : "+f"((c)[0]), "+f"((c)[1]), "+f"((c)[2]), "+f"((c)[3]) \
        : "r"((a)[0]), "r"((a)[1]), "r"((a)[2]), "r"((a)[3]), \
          "r"((b)[0]), "r"((b)[1]))

// ---- 2-term core: C = A16·Bh + A16·Bl (3 arrays/stage, 60 KB total)
#define G3STAGE (3 * GARR)
#define GEMM3_SMEM (2 * G3STAGE * 2)

__device__ __forceinline__ void gemm16_2term(
    const __half* __restrict__ A16,
    const __half* __restrict__ Bh, const __half* __restrict__ Bl,
    int mBase, float acc[2][8][4], __half* smem)
{
    const int tid  = threadIdx.x;
    const int wid  = tid >> 5;
    const int lane = tid & 31;
    const int wm = (wid & 3) * 32;
    const int wn = (wid >> 2) * 64;
    const int g = lane >> 2;
    const int t = lane & 3;

    const u32 sbase = (u32)__cvta_generic_to_shared(smem);

#pragma unroll
    for (int am = 0; am < 2; am++)
#pragma unroll
        for (int an = 0; an < 8; an++)
#pragma unroll
            for (int c = 0; c < 4; c++) acc[am][an][c] = 0.f;

    auto issue_tile = [&](int k0, int st) {
        const u32 b0 = sbase + (u32)st * (G3STAGE * 2);
#pragma unroll
        for (int it = 0; it < 2; it++) {
            const int idx = tid + it * 256;
            const int r = idx >> 2;
            const int c = idx & 3;
            const u32 doff = (u32)(r * SSTR + c * 8) * 2;
            const size_t aoff = (size_t)(mBase + r) * DMODEL + k0 + c * 8;
            const size_t boff = (size_t)r * DMODEL + k0 + c * 8;
            cpa16(b0 + doff,                 A16 + aoff);
            cpa16(b0 + GARR * 2 + doff,      Bh + boff);
            cpa16(b0 + 2 * GARR * 2 + doff,  Bl + boff);
        }
        CP_COMMIT();
    };

    const int NKT = DMODEL / KC;
    issue_tile(0, 0);

    for (int kt = 0; kt < NKT; kt++) {
        const int cur = kt & 1;
        CP_WAIT0();
        __syncthreads();
        if (kt + 1 < NKT) issue_tile((kt + 1) * KC, 1 - cur);

        const __half* sA  = smem + cur * G3STAGE;
        const __half* sBh = sA + GARR;
        const __half* sBl = sBh + GARR;

#pragma unroll
        for (int ks = 0; ks < KC; ks += 16) {
            u32 af[2][4];
#pragma unroll
            for (int am = 0; am < 2; am++) {
                const int r0 = wm + am * 16 + g;
                af[am][0] = *(const u32*)&sA[(r0    ) * SSTR + ks + 2 * t];
                af[am][1] = *(const u32*)&sA[(r0 + 8) * SSTR + ks + 2 * t];
                af[am][2] = *(const u32*)&sA[(r0    ) * SSTR + ks + 2 * t + 8];
                af[am][3] = *(const u32*)&sA[(r0 + 8) * SSTR + ks + 2 * t + 8];
            }
            u32 bfh[8][2], bfl[8][2];
#pragma unroll
            for (int an = 0; an < 8; an++) {
                const int n = wn + an * 8 + g;
                bfh[an][0] = *(const u32*)&sBh[n * SSTR + ks + 2 * t];
                bfh[an][1] = *(const u32*)&sBh[n * SSTR + ks + 2 * t + 8];
                bfl[an][0] = *(const u32*)&sBl[n * SSTR + ks + 2 * t];
                bfl[an][1] = *(const u32*)&sBl[n * SSTR + ks + 2 * t + 8];
            }
#pragma unroll
            for (int am = 0; am < 2; am++)
#pragma unroll
                for (int an = 0; an < 8; an++) {
                    MMA_F16(acc[am][an], af[am], bfh[an]);
                    MMA_F16(acc[am][an], af[am], bfl[an]);
                }
        }
    }
}

// ---- 1-term core: C = A16·B16 (2 arrays/stage, 40 KB total)
#define G2STAGE (2 * GARR)
#define GEMM2_SMEM (2 * G2STAGE * 2)

__device__ __forceinline__ void gemm16_1term(
    const __half* __restrict__ A16, const __half* __restrict__ B16,
    int mBase, float acc[2][8][4], __half* smem)
{
    const int tid  = threadIdx.x;
    const int wid  = tid >> 5;
    const int lane = tid & 31;
    const int wm = (wid & 3) * 32;
    const int wn = (wid >> 2) * 64;
    const int g = lane >> 2;
    const int t = lane & 3;

    const u32 sbase = (u32)__cvta_generic_to_shared(smem);

#pragma unroll
    for (int am = 0; am < 2; am++)
#pragma unroll
        for (int an = 0; an < 8; an++)
#pragma unroll
            for (int c = 0; c < 4; c++) acc[am][an][c] = 0.f;

    auto issue_tile = [&](int k0, int st) {
        const u32 b0 = sbase + (u32)st * (G2STAGE * 2);
#pragma unroll
        for (int it = 0; it < 2; it++) {
            const int idx = tid + it * 256;
            const int r = idx >> 2;
            const int c = idx & 3;
            const u32 doff = (u32)(r * SSTR + c * 8) * 2;
            cpa16(b0 + doff,            A16 + (size_t)(mBase + r) * DMODEL + k0 + c * 8);
            cpa16(b0 + GARR * 2 + doff, B16 + (size_t)r * DMODEL + k0 + c * 8);
        }
        CP_COMMIT();
    };

    const int NKT = DMODEL / KC;
    issue_tile(0, 0);

    for (int kt = 0; kt < NKT; kt++) {
        const int cur = kt & 1;
        CP_WAIT0();
        __syncthreads();
        if (kt + 1 < NKT) issue_tile((kt + 1) * KC, 1 - cur);

        const __half* sA = smem + cur * G2STAGE;
        const __half* sB = sA + GARR;

#pragma unroll
        for (int ks = 0; ks < KC; ks += 16) {
            u32 af[2][4];
#pragma unroll
            for (int am = 0; am < 2; am++) {
                const int r0 = wm + am * 16 + g;
                af[am][0] = *(const u32*)&sA[(r0    ) * SSTR + ks + 2 * t];
                af[am][1] = *(const u32*)&sA[(r0 + 8) * SSTR + ks + 2 * t];
                af[am][2] = *(const u32*)&sA[(r0    ) * SSTR + ks + 2 * t + 8];
                af[am][3] = *(const u32*)&sA[(r0 + 8) * SSTR + ks + 2 * t + 8];
            }
            u32 bf[8][2];
#pragma unroll
            for (int an = 0; an < 8; an++) {
                const int n = wn + an * 8 + g;
                bf[an][0] = *(const u32*)&sB[n * SSTR + ks + 2 * t];
                bf[an][1] = *(const u32*)&sB[n * SSTR + ks + 2 * t + 8];
            }
#pragma unroll
            for (int am = 0; am < 2; am++)
#pragma unroll
                for (int an = 0; an < 8; an++)
                    MMA_F16(acc[am][an], af[am], bf[an]);
        }
    }
}

// projections: grid (M/128, NHEADS, 3). z: 0->q, 1->k, 2->v.
// Writes single fp16 in [b,h,s,d]. Non-divergent epilogue.
__global__ void __launch_bounds__(256) proj_kernel(
    const float* __restrict__ bQ, const float* __restrict__ bK, const float* __restrict__ bV)
{
    extern __shared__ __half smem[];
    const int mBase = blockIdx.x * 128;
    const int h     = blockIdx.y;
    const int which = blockIdx.z;
    const float* bias = ((which == 0) ? bQ : (which == 1) ? bK : bV) + h * DHEAD;
    __half* dst16 = (which == 0) ? gq16 : (which == 1) ? gk16 : gv16;
    const __half* Bh = gw16_hi + (size_t)(which * NHEADS + h) * DHEAD * DMODEL;
    const __half* Bl = gw16_lo + (size_t)(which * NHEADS + h) * DHEAD * DMODEL;

    float acc[2][8][4];
    gemm16_2term(gx16, Bh, Bl, mBase, acc, smem);

    const int tid = threadIdx.x, wid = tid >> 5, lane = tid & 31;
    const int wm = (wid & 3) * 32, wn = (wid >> 2) * 64;
    const int g = lane >> 2, t = lane & 3;

#pragma unroll
    for (int am = 0; am < 2; am++)
#pragma unroll
        for (int an = 0; an < 8; an++) {
            const int col = wn + an * 8 + 2 * t;
            const float b0 = bias[col], b1 = bias[col + 1];
#pragma unroll
            for (int half = 0; half < 2; half++) {
                const int m = mBase + wm + am * 16 + g + 8 * half;
                const int bb = m >> 11;
                const int s  = m & (SEQLEN - 1);
                const size_t dst = (((size_t)(bb * NHEADS + h) * SEQLEN + s) * DHEAD + col);
                float v0 = acc[am][an][2 * half + 0] + b0;
                float v1 = acc[am][an][2 * half + 1] + b1;
                __half2 p; p.x = __float2half(v0); p.y = __float2half(v1);
                *(__half2*)&dst16[dst] = p;
            }
        }
}

// out proj: grid (M/128, DMODEL/128), block 256. Single-term fp16.
__global__ void __launch_bounds__(256) out_mma_kernel(
    const float* __restrict__ bO, float* __restrict__ out)
{
    extern __shared__ __half smem[];
    const int mBase = blockIdx.x * 128;
    const int nBase = blockIdx.y * 128;
    float acc[2][8][4];
    gemm16_1term(gz16, gwo16 + (size_t)nBase * DMODEL, mBase, acc, smem);

    const int tid = threadIdx.x, wid = tid >> 5, lane = tid & 31;
    const int wm = (wid & 3) * 32, wn = (wid >> 2) * 64;
    const int g = lane >> 2, t = lane & 3;
    float* outBase = out + (size_t)mBase * DMODEL + nBase;
#pragma unroll
    for (int am = 0; am < 2; am++)
#pragma unroll
        for (int an = 0; an < 8; an++) {
            const int col = wn + an * 8 + 2 * t;
            const int r0 = wm + am * 16 + g;
            float b0 = bO[nBase + col], b1 = bO[nBase + col + 1];
            outBase[(size_t)r0 * DMODEL + col]           = acc[am][an][0] + b0;
            outBase[(size_t)r0 * DMODEL + col + 1]       = acc[am][an][1] + b1;
            outBase[(size_t)(r0 + 8) * DMODEL + col]     = acc[am][an][2] + b0;
            outBase[(size_t)(r0 + 8) * DMODEL + col + 1] = acc[am][an][3] + b1;
        }
}

// ---------------------------------------------------------------------------
// fp16 flash attention: S = Q16·K16 ; O = P16·V16 (single-term both).
// cp.async 2-stage K/V pipeline (2 arrays), one sync/iter.
// grid = (SEQLEN/128, NHEADS, BATCH), block = 256 (8 warps).
// ---------------------------------------------------------------------------
#define ASTR 136
#define AARR (64 * ASTR)
#define ASTAGE (2 * AARR)           // k16, v16
#define AQ (128 * ASTR)
#define ATTN_SMEM ((AQ + 2 * ASTAGE) * 2)

__global__ void __launch_bounds__(256, 1) attn_mma_kernel()
{
    const int qt = gridDim.x - 1 - blockIdx.x;
    const int h  = blockIdx.y;
    const int b  = blockIdx.z;
    const int qBase = qt * 128;

    extern __shared__ __half smem_a[];
    __half* sQ  = smem_a;          // [128][ASTR]
    __half* kvs = sQ + AQ;         // 2 stages x [2][64][ASTR]

    const int tid = threadIdx.x;
    const int wid = tid >> 5;
    const int lane = tid & 31;
    const int g = lane >> 2;
    const int t = lane & 3;
    const int wrow = wid * 16;

    const size_t bh = (size_t)(b * NHEADS + h) * SEQLEN * DHEAD;
    const __half* q = gq16 + bh;
    const __half* k = gk16 + bh;
    const __half* v = gv16 + bh;

    const u32 kvbase = (u32)__cvta_generic_to_shared(kvs);

    auto issue_kv = [&](int kBase, int st) {
        const u32 b0 = kvbase + (u32)st * (ASTAGE * 2);
#pragma unroll
        for (int it = 0; it < 4; it++) {
            const int idx = tid + it * 256;
            const int r = idx >> 4;
            const int c = idx & 15;
            const u32 doff = (u32)(r * ASTR + c * 8) * 2;
            const size_t goff = (size_t)(kBase + r) * DHEAD + c * 8;
            cpa16(b0 + doff,            k + goff);
            cpa16(b0 + AARR * 2 + doff, v + goff);
        }
        CP_COMMIT();
    };

    const int nkt = 2 * qt + 2;
    issue_kv(0, 0);

    for (int idx = tid; idx < 128 * 16; idx += 256) {
        const int r = idx >> 4, c8 = (idx & 15) * 8;
        *(uint4*)&sQ[r * ASTR + c8] = *(const uint4*)&q[(size_t)(qBase + r) * DHEAD + c8];
    }

    float o[16][4];
#pragma unroll
    for (int j = 0; j < 16; j++)
#pragma unroll
        for (int c = 0; c < 4; c++) o[j][c] = 0.f;
    float m0 = -1e30f, m1 = -1e30f, l0 = 0.f, l1 = 0.f;

    const float sl2e = 0.08838834764831845f * 1.4426950408889634f;

    for (int kt = 0; kt < nkt; kt++) {
        const int kBase = kt * 64;
        const int cur = kt & 1;
        CP_WAIT0();
        __syncthreads();
        if (kt + 1 < nkt) issue_kv((kt + 1) * 64, 1 - cur);

        if (kBase > qBase + wrow + 15) continue;

        const __half* sK = kvs + cur * ASTAGE;
        const __half* sV = sK + AARR;

        float sacc[8][4];
#pragma unroll
        for (int an = 0; an < 8; an++)
#pragma unroll
            for (int c = 0; c < 4; c++) sacc[an][c] = 0.f;

#pragma unroll
        for (int ks = 0; ks < DHEAD; ks += 16) {
            u32 aq[4];
            const int r0 = wrow + g;
            aq[0] = *(const u32*)&sQ[(r0    ) * ASTR + ks + 2 * t];
            aq[1] = *(const u32*)&sQ[(r0 + 8) * ASTR + ks + 2 * t];
            aq[2] = *(const u32*)&sQ[(r0    ) * ASTR + ks + 2 * t + 8];
            aq[3] = *(const u32*)&sQ[(r0 + 8) * ASTR + ks + 2 * t + 8];
            u32 bk[8][2];
#pragma unroll
            for (int an = 0; an < 8; an++) {
                const int n = an * 8 + g;
                bk[an][0] = *(const u32*)&sK[n * ASTR + ks + 2 * t];
                bk[an][1] = *(const u32*)&sK[n * ASTR + ks + 2 * t + 8];
            }
#pragma unroll
            for (int an = 0; an < 8; an++) MMA_F16(sacc[an], aq, bk[an]);
        }

        const int qr0 = qBase + wrow + g;
        const int qr1 = qr0 + 8;
#pragma unroll
        for (int an = 0; an < 8; an++) {
            const int c0 = kBase + an * 8 + 2 * t;
            sacc[an][0] = (c0     <= qr0) ? sacc[an][0] * sl2e : -1e30f;
            sacc[an][1] = (c0 + 1 <= qr0) ? sacc[an][1] * sl2e : -1e30f;
            sacc[an][2] = (c0     <= qr1) ? sacc[an][2] * sl2e : -1e30f;
            sacc[an][3] = (c0 + 1 <= qr1) ? sacc[an][3] * sl2e : -1e30f;
        }

        float mx0 = -1e30f, mx1 = -1e30f;
#pragma unroll
        for (int an = 0; an < 8; an++) {
            mx0 = fmaxf(mx0, fmaxf(sacc[an][0], sacc[an][1]));
            mx1 = fmaxf(mx1, fmaxf(sacc[an][2], sacc[an][3]));
        }
        mx0 = fmaxf(mx0, __shfl_xor_sync(0xffffffffu, mx0, 1));
        mx0 = fmaxf(mx0, __shfl_xor_sync(0xffffffffu, mx0, 2));
        mx1 = fmaxf(mx1, __shfl_xor_sync(0xffffffffu, mx1, 1));
        mx1 = fmaxf(mx1, __shfl_xor_sync(0xffffffffu, mx1, 2));

        const float mn0 = fmaxf(m0, mx0), mn1 = fmaxf(m1, mx1);
        const float al0 = ex2f(m0 - mn0), al1 = ex2f(m1 - mn1);
        m0 = mn0; m1 = mn1;

        float s0 = 0.f, s1 = 0.f;
#pragma unroll
        for (int an = 0; an < 8; an++) {
            sacc[an][0] = ex2f(sacc[an][0] - mn0);
            sacc[an][1] = ex2f(sacc[an][1] - mn0);
            sacc[an][2] = ex2f(sacc[an][2] - mn1);
            sacc[an][3] = ex2f(sacc[an][3] - mn1);
            s0 += sacc[an][0] + sacc[an][1];
            s1 += sacc[an][2] + sacc[an][3];
        }
        s0 += __shfl_xor_sync(0xffffffffu, s0, 1);
        s0 += __shfl_xor_sync(0xffffffffu, s0, 2);
        s1 += __shfl_xor_sync(0xffffffffu, s1, 1);
        s1 += __shfl_xor_sync(0xffffffffu, s1, 2);
        l0 = l0 * al0 + s0;
        l1 = l1 * al1 + s1;

#pragma unroll
        for (int j = 0; j < 16; j++) {
            o[j][0] *= al0; o[j][1] *= al0;
            o[j][2] *= al1; o[j][3] *= al1;
        }

        const u16* sV16 = (const u16*)sV;
#pragma unroll
        for (int jp = 0; jp < 4; jp++) {
            u32 ap[4];
            ap[0] = pack2h(sacc[2 * jp][0],     sacc[2 * jp][1]);
            ap[1] = pack2h(sacc[2 * jp][2],     sacc[2 * jp][3]);
            ap[2] = pack2h(sacc[2 * jp + 1][0], sacc[2 * jp + 1][1]);
            ap[3] = pack2h(sacc[2 * jp + 1][2], sacc[2 * jp + 1][3]);
            const int ks = 16 * jp;
#pragma unroll
            for (int anp = 0; anp < 2; anp++) {
                u32 vb[8][2];
#pragma unroll
                for (int aj = 0; aj < 8; aj++) {
                    const int n = (anp * 8 + aj) * 8 + g;
                    u32 v0 = sV16[(ks + 2 * t)     * ASTR + n];
                    u32 v1 = sV16[(ks + 2 * t + 1) * ASTR + n];
                    u32 v8 = sV16[(ks + 2 * t + 8) * ASTR + n];
                    u32 v9 = sV16[(ks + 2 * t + 9) * ASTR + n];
                    vb[aj][0] = v0 | (v1 << 16);
                    vb[aj][1] = v8 | (v9 << 16);
                }
#pragma unroll
                for (int aj = 0; aj < 8; aj++) MMA_F16(o[anp * 8 + aj], ap, vb[aj]);
            }
        }
    }

    // epilogue: z = O / l -> fp16 single
    const float inv0 = 1.f / l0;
    const float inv1 = 1.f / l1;
    const int r0 = qBase + wrow + g;
#pragma unroll
    for (int an = 0; an < 16; an++) {
        const int col = an * 8 + 2 * t;
#pragma unroll
        for (int half = 0; half < 2; half++) {
            const int row = r0 + 8 * half;
            const float inv = half ? inv1 : inv0;
            float z0 = o[an][2 * half + 0] * inv;
            float z1 = o[an][2 * half + 1] * inv;
            __half2 zp; zp.x = __float2half(z0); zp.y = __float2half(z1);
            const size_t dst = ((size_t)(b * SEQLEN + row) * DMODEL + h * DHEAD + col);
            *(__half2*)&gz16[dst] = zp;
        }
    }
}

// ---------------------------------------------------------------------------
// Launch
// ---------------------------------------------------------------------------
extern "C" void kernel_launch(void* const* d_in, const int* in_sizes, int n_in,
                              void* d_out, int out_size)
{
    const float* x  = (const float*)d_in[0];
    const float* Wq = (const float*)d_in[1];
    const float* Wk = (const float*)d_in[2];
    const float* Wv = (const float*)d_in[3];
    const float* Wo = (const float*)d_in[4];
    const float* bQ = (const float*)d_in[5];
    const float* bK = (const float*)d_in[6];
    const float* bV = (const float*)d_in[7];
    const float* bO = (const float*)d_in[8];
    float* out = (float*)d_out;

    static bool attr_set = false;
    if (!attr_set) {
        cudaFuncSetAttribute(proj_kernel, cudaFuncAttributeMaxDynamicSharedMemorySize, GEMM3_SMEM);
        cudaFuncSetAttribute(out_mma_kernel, cudaFuncAttributeMaxDynamicSharedMemorySize, GEMM2_SMEM);
        cudaFuncSetAttribute(attn_mma_kernel, cudaFuncAttributeMaxDynamicSharedMemorySize, ATTN_SMEM);
        attr_set = true;
    }

    // 0) splits (x -> fp16; QKV weights -> fp16 hi/lo; Wo -> fp16)
    split_x_kernel<<<(MTOT * DMODEL / 2) / 256, 256>>>(x);
    split_w_kernel<<<dim3(DMODEL / 32, DHEAD / 32, 3 * NHEADS), dim3(32, 8)>>>(Wq, Wk, Wv);
    split_wo_kernel<<<dim3(DMODEL / 32, DMODEL / 32), dim3(32, 8)>>>(Wo);

    // 1) q/k/v projections (fp16 2-term on weights; single fp16 outputs)
    proj_kernel<<<dim3(MTOT / 128, NHEADS, 3), 256, GEMM3_SMEM>>>(bQ, bK, bV);

    // 2) fp16 flash attention (single-term S and PV)
    attn_mma_kernel<<<dim3(SEQLEN / 128, NHEADS, BATCH), 256, ATTN_SMEM>>>();

    // 3) output projection (single-term fp16)
    out_mma_kernel<<<dim3(MTOT / 128, DMODEL / 128), 256, GEMM2_SMEM>>>(bO, out);

    (void)in_sizes; (void)n_in; (void)out_size;
}